// round 1
// baseline (speedup 1.0000x reference)
#include <cuda_runtime.h>
#include <math.h>

#define B    8
#define S    256
#define H    768
#define P    256
#define NE   20000
#define NT   100000
#define NR   200
#define HOPS 3

// ---------------- scratch (device globals; no allocation) ----------------
__device__ float g_wvp[H];
__device__ float g_slogit[B * S];
__device__ float g_D[B * H];
__device__ float g_R[B * HOPS * NR];
__device__ float g_CS[B * HOPS * 2];
__device__ float g_walked[B * NE];
__device__ float g_walk[B * HOPS * NE];
__device__ float g_sums[B];
__device__ float g_LD[B * H];
__device__ float g_scores[B * NE];

// ---------------- helpers ----------------
__device__ __forceinline__ float warpSum(float v) {
    #pragma unroll
    for (int o = 16; o; o >>= 1) v += __shfl_xor_sync(0xffffffffu, v, o);
    return v;
}
__device__ __forceinline__ float warpMax(float v) {
    #pragma unroll
    for (int o = 16; o; o >>= 1) v = fmaxf(v, __shfl_xor_sync(0xffffffffu, v, o));
    return v;
}

// ---------------- kernels ----------------

// zero g_walked and g_D
__global__ void k_zero() {
    int i = blockIdx.x * blockDim.x + threadIdx.x;
    if (i < B * NE) g_walked[i] = 0.f;
    if (i < B * H)  g_D[i] = 0.f;
}

// wvp[h] = sum_p W_v[h,p] * W_p[p]   (warp per h)
__global__ void k_wvp(const float* __restrict__ Wv, const float* __restrict__ Wp) {
    int warp = (blockIdx.x * blockDim.x + threadIdx.x) >> 5;
    int lane = threadIdx.x & 31;
    if (warp >= H) return;
    float acc = 0.f;
    for (int p = lane; p < P; p += 32) acc += Wv[warp * P + p] * Wp[p];
    acc = warpSum(acc);
    if (lane == 0) g_wvp[warp] = acc;
}

// slogit[b,s] = dot(lhs[b,s,:], wvp)   (warp per row)
__global__ void k_logit(const float* __restrict__ lhs) {
    __shared__ float sw[H];
    for (int i = threadIdx.x; i < H; i += blockDim.x) sw[i] = g_wvp[i];
    __syncthreads();
    int warp = threadIdx.x >> 5, lane = threadIdx.x & 31;
    int row = blockIdx.x * 8 + warp;   // row < B*S
    const float* base = lhs + (size_t)row * H;
    float acc = 0.f;
    for (int h = lane; h < H; h += 32) acc += base[h] * sw[h];
    acc = warpSum(acc);
    if (lane == 0) g_slogit[row] = acc;
}

// softmax over s (per b) then D[b,h] = sum_s p[s]*mask[b,s]*lhs[b,s,h]
// 4 blocks per b, each handles a 64-row s-segment, atomic-accumulates into g_D
__global__ void k_D(const float* __restrict__ lhs, const float* __restrict__ mask) {
    int b = blockIdx.x >> 2;
    int seg = blockIdx.x & 3;
    int tid = threadIdx.x;              // 256 threads
    int lane = tid & 31, wid = tid >> 5;
    __shared__ float sl[S];
    __shared__ float red[8];

    float l = g_slogit[b * S + tid];
    // block max (256)
    float m = warpMax(l);
    if (lane == 0) red[wid] = m;
    __syncthreads();
    if (tid == 0) {
        float mm = red[0];
        #pragma unroll
        for (int i = 1; i < 8; i++) mm = fmaxf(mm, red[i]);
        red[0] = mm;
    }
    __syncthreads();
    float mx = red[0];
    __syncthreads();
    float e = expf(l - mx);
    float s = warpSum(e);
    if (lane == 0) red[wid] = s;
    __syncthreads();
    if (tid == 0) {
        float ss = 0.f;
        #pragma unroll
        for (int i = 0; i < 8; i++) ss += red[i];
        red[0] = ss;
    }
    __syncthreads();
    float inv = 1.f / red[0];
    sl[tid] = e * inv * mask[b * S + tid];
    __syncthreads();

    float a0 = 0.f, a1 = 0.f, a2 = 0.f;
    int s0 = seg * 64;
    for (int si = s0; si < s0 + 64; si++) {
        const float* r = lhs + (size_t)(b * S + si) * H;
        float w = sl[si];
        a0 += w * r[tid];
        a1 += w * r[tid + 256];
        a2 += w * r[tid + 512];
    }
    atomicAdd(&g_D[b * H + tid],       a0);
    atomicAdd(&g_D[b * H + tid + 256], a1);
    atomicAdd(&g_D[b * H + tid + 512], a2);
}

// rels_seq softmax (200-wide) and checks_seq softmax (2-wide), block per (b,hop)
__global__ void k_rels(const float* __restrict__ Wr, const float* __restrict__ Wc) {
    int b = blockIdx.x / HOPS, hop = blockIdx.x % HOPS;
    int tid = threadIdx.x;              // 256
    int lane = tid & 31, wid = tid >> 5;
    __shared__ float sD[H];
    __shared__ float sm[NR];
    __shared__ float scv[2];
    __shared__ float red[8];
    for (int i = tid; i < H; i += 256) sD[i] = g_D[b * H + i];
    __syncthreads();

    if (tid < NR) {
        float acc = 0.f;
        for (int h = 0; h < H; h++) acc += sD[h] * Wr[h * (HOPS * NR) + hop * NR + tid];
        sm[tid] = acc;
    }
    if (tid >= 200 && tid < 202) {
        int c = tid - 200;
        float acc = 0.f;
        for (int h = 0; h < H; h++) acc += sD[h] * Wc[h * (HOPS * 2) + hop * 2 + c];
        scv[c] = acc;
    }
    __syncthreads();

    // block softmax over 200 entries
    float v = (tid < NR) ? sm[tid] : -INFINITY;
    float m = warpMax(v);
    if (lane == 0) red[wid] = m;
    __syncthreads();
    if (tid == 0) {
        float mm = red[0];
        #pragma unroll
        for (int i = 1; i < 8; i++) mm = fmaxf(mm, red[i]);
        red[0] = mm;
    }
    __syncthreads();
    float mx = red[0];
    __syncthreads();
    float e = (tid < NR) ? expf(sm[tid] - mx) : 0.f;
    float s = warpSum(e);
    if (lane == 0) red[wid] = s;
    __syncthreads();
    if (tid == 0) {
        float ss = 0.f;
        #pragma unroll
        for (int i = 0; i < 8; i++) ss += red[i];
        red[0] = ss;
    }
    __syncthreads();
    if (tid < NR) g_R[(b * HOPS + hop) * NR + tid] = e / red[0];

    if (tid == 0) {
        float c0 = scv[0], c1 = scv[1];
        float m2 = fmaxf(c0, c1);
        float e0 = expf(c0 - m2), e1 = expf(c1 - m2);
        float inv = 1.f / (e0 + e1);
        g_CS[(b * HOPS + hop) * 2 + 0] = e0 * inv;
        g_CS[(b * HOPS + hop) * 2 + 1] = e1 * inv;
    }
}

// LD[b,:] = D[b,:] @ L_w   (block per b)
__global__ void k_LD(const float* __restrict__ Lw) {
    int b = blockIdx.x;
    int tid = threadIdx.x;  // 256
    __shared__ float sD[H];
    for (int i = tid; i < H; i += 256) sD[i] = g_D[b * H + i];
    __syncthreads();
    float a0 = 0.f, a1 = 0.f, a2 = 0.f;
    for (int h = 0; h < H; h++) {
        float d = sD[h];
        const float* r = Lw + (size_t)h * H;
        a0 += d * r[tid];
        a1 += d * r[tid + 256];
        a2 += d * r[tid + 512];
    }
    g_LD[b * H + tid]       = a0;
    g_LD[b * H + tid + 256] = a1;
    g_LD[b * H + tid + 512] = a2;
}

// scores[b,e] = LD[b,:] . sum_t EE[e,t,:]    (warp per e, t-reduced first)
__global__ void k_scores(const float* __restrict__ EE) {
    __shared__ float4 sLD[B * 192];     // 24 KB
    const float4* LD4 = (const float4*)g_LD;
    for (int i = threadIdx.x; i < B * 192; i += blockDim.x) sLD[i] = LD4[i];
    __syncthreads();
    int warp = threadIdx.x >> 5, lane = threadIdx.x & 31;
    int e = blockIdx.x * 8 + warp;
    if (e >= NE) return;
    const float4* base = (const float4*)(EE + (size_t)e * 3072);
    float acc[B];
    #pragma unroll
    for (int b = 0; b < B; b++) acc[b] = 0.f;
    for (int j = lane; j < 192; j += 32) {
        float4 v0 = base[j], v1 = base[j + 192], v2 = base[j + 384], v3 = base[j + 576];
        float4 sx;
        sx.x = v0.x + v1.x + v2.x + v3.x;
        sx.y = v0.y + v1.y + v2.y + v3.y;
        sx.z = v0.z + v1.z + v2.z + v3.z;
        sx.w = v0.w + v1.w + v2.w + v3.w;
        #pragma unroll
        for (int b = 0; b < B; b++) {
            float4 l = sLD[b * 192 + j];
            acc[b] += sx.x * l.x + sx.y * l.y + sx.z * l.z + sx.w * l.w;
        }
    }
    #pragma unroll
    for (int b = 0; b < B; b++) {
        float v = warpSum(acc[b]);
        if (lane == 0) g_scores[b * NE + e] = v;
    }
}

// one hop: trip = R[b,hop,rel] * e_prev[head]; atomic scatter by tail
__global__ void k_scatter(int hop, const float* __restrict__ init_ent,
                          const int* __restrict__ heads,
                          const int* __restrict__ rels,
                          const int* __restrict__ tails) {
    int idx = blockIdx.x * blockDim.x + threadIdx.x;
    if (idx >= B * NT) return;
    int b = idx / NT;
    int h = heads[idx];
    int r = rels[idx];
    int t = tails[idx];
    const float* esrc = (hop == 0) ? (init_ent + b * NE)
                                   : (g_walk + (size_t)(b * HOPS + hop - 1) * NE);
    float trip = g_R[(b * HOPS + hop) * NR + r] * esrc[h];
    atomicAdd(&g_walked[b * NE + t], trip);
}

// per-b sum of walked
__global__ void k_sum() {
    int b = blockIdx.x;
    int tid = threadIdx.x;  // 1024
    int lane = tid & 31, wid = tid >> 5;
    __shared__ float red[32];
    float s = 0.f;
    for (int e = tid; e < NE; e += 1024) s += g_walked[b * NE + e];
    s = warpSum(s);
    if (lane == 0) red[wid] = s;
    __syncthreads();
    if (tid < 32) {
        float v = red[tid];
        v = warpSum(v);
        if (tid == 0) g_sums[b] = v;
    }
}

// normalize into g_walk[b,hop,:], re-zero g_walked for next hop
__global__ void k_norm(int hop) {
    int i = blockIdx.x * blockDim.x + threadIdx.x;
    if (i >= B * NE) return;
    int b = i / NE;
    int e = i - b * NE;
    float v = g_walked[i];
    g_walk[(size_t)(b * HOPS + hop) * NE + e] = v / (g_sums[b] + 1e-6f);
    g_walked[i] = 0.f;
}

// checks softmax over NE + final combine, block per (b,hop)
__global__ void k_final(float* __restrict__ out) {
    int bh = blockIdx.x;
    int b = bh / HOPS;
    const float* w  = g_walk   + (size_t)bh * NE;
    const float* sc = g_scores + (size_t)b * NE;
    int tid = threadIdx.x;   // 1024
    int lane = tid & 31, wid = tid >> 5;
    __shared__ float red[32];
    __shared__ float sbc;

    float m = -INFINITY;
    for (int e = tid; e < NE; e += 1024) m = fmaxf(m, w[e] * sc[e]);
    m = warpMax(m);
    if (lane == 0) red[wid] = m;
    __syncthreads();
    if (tid < 32) {
        float v = red[tid];
        v = warpMax(v);
        if (tid == 0) sbc = v;
    }
    __syncthreads();
    float mx = sbc;
    __syncthreads();

    float s = 0.f;
    for (int e = tid; e < NE; e += 1024) s += expf(w[e] * sc[e] - mx);
    s = warpSum(s);
    if (lane == 0) red[wid] = s;
    __syncthreads();
    if (tid < 32) {
        float v = red[tid];
        v = warpSum(v);
        if (tid == 0) sbc = v;
    }
    __syncthreads();
    float inv = 1.f / sbc;
    float c0 = g_CS[bh * 2 + 0];
    float c1 = g_CS[bh * 2 + 1];
    for (int e = tid; e < NE; e += 1024) {
        float we = w[e];
        out[(size_t)bh * NE + e] = c0 * we + c1 * expf(we * sc[e] - mx) * inv;
    }
}

// ---------------- launcher ----------------
extern "C" void kernel_launch(void* const* d_in, const int* in_sizes, int n_in,
                              void* d_out, int out_size) {
    const float* lhs      = (const float*)d_in[0];   // (B,S,H)
    const float* mask     = (const float*)d_in[1];   // (B,S)
    const float* init_ent = (const float*)d_in[2];   // (B,NE)
    const float* EE       = (const float*)d_in[3];   // (NE,4,H)
    // d_in[4] = W_q  (eliminated: constant term cancels in softmax)
    const float* Wv       = (const float*)d_in[5];   // (H,P)
    const float* Wp       = (const float*)d_in[6];   // (P,1)
    const float* Wr       = (const float*)d_in[7];   // (H, HOPS*NR)
    const float* Wc       = (const float*)d_in[8];   // (H, HOPS*2)
    const float* Lw       = (const float*)d_in[9];   // (H,H)
    const int*   heads    = (const int*)d_in[10];    // (B,NT)
    const int*   rels     = (const int*)d_in[11];
    const int*   tails    = (const int*)d_in[12];
    float* out = (float*)d_out;                      // (B,HOPS,NE)

    k_zero  <<<(B * NE + 255) / 256, 256>>>();
    k_wvp   <<<(H * 32 + 255) / 256, 256>>>(Wv, Wp);
    k_logit <<<(B * S) / 8, 256>>>(lhs);
    k_D     <<<B * 4, 256>>>(lhs, mask);
    k_rels  <<<B * HOPS, 256>>>(Wr, Wc);
    k_LD    <<<B, 256>>>(Lw);
    k_scores<<<NE / 8, 256>>>(EE);
    for (int hop = 0; hop < HOPS; hop++) {
        k_scatter<<<(B * NT + 255) / 256, 256>>>(hop, init_ent, heads, rels, tails);
        k_sum    <<<B, 1024>>>();
        k_norm   <<<(B * NE + 255) / 256, 256>>>(hop);
    }
    k_final <<<B * HOPS, 1024>>>(out);
}